// round 2
// baseline (speedup 1.0000x reference)
#include <cuda_runtime.h>
#include <cstddef>

// RoiAlign: 4-level FPN, B=2, N=1000, C=256, POOL=7
// out[B, N, 7, 7, C] float32
// Inputs (metadata order): feat0 [2,256,256,256], feat1 [2,128,128,256],
//                          feat2 [2,64,64,256],  feat3 [2,32,32,256],
//                          proposals [2,1000,4]  (x1,y1,x2,y2 in [0,1])

#define POOL 7
#define C_CH 256

__global__ __launch_bounds__(256, 8)
void roi_align_kernel(const float* __restrict__ f0,
                      const float* __restrict__ f1,
                      const float* __restrict__ f2,
                      const float* __restrict__ f3,
                      const float* __restrict__ props,
                      float* __restrict__ out,
                      int N)
{
    const int roi = blockIdx.x;          // 0 .. B*N-1
    const int b   = roi / N;

    // box
    const float4 box = reinterpret_cast<const float4*>(props)[roi];
    const float x1 = box.x, y1 = box.y, x2 = box.z, y2 = box.w;

    // ---- level selection (replicates reference fp32 math exactly) ----
    const float area  = (y2 - y1) * (x2 - x1);
    const float canon = 56.0f / 1024.0f + 1e-6f;  // 56/sqrt(1024*1024)+1e-6
    const float lf = floorf(logf(sqrtf(area) / canon) / logf(2.0f));
    // nan / -inf / negative -> level 0 ; clip to [0,3]
    int lvl = 0;
    if (lf >= 3.0f)       lvl = 3;
    else if (lf >= 1.0f)  lvl = (int)lf;

    const int H = 256 >> lvl;
    const int W = 256 >> lvl;
    const float* f = (lvl == 0) ? f0 : (lvl == 1) ? f1 : (lvl == 2) ? f2 : f3;
    const float* fb = f + (size_t)b * H * W * C_CH;

    // ---- per-ROI sample coordinate tables (7 y's, 7 x's) ----
    __shared__ int   s_ty[POOL], s_by[POOL], s_tx[POOL], s_bx[POOL];
    __shared__ float s_ly[POOL], s_lx[POOL];

    if (threadIdx.x < POOL) {
        const int r = threadIdx.x;
        const float rf = (float)r;
        const float Hf = (float)(H)-1.0f;  // (Hl - 1)
        const float Wf = (float)(W)-1.0f;

        const float in_y = y1 * Hf + rf * ((y2 - y1) * Hf / (float)(POOL - 1));
        const float in_x = x1 * Wf + rf * ((x2 - x1) * Wf / (float)(POOL - 1));

        const float tyf = floorf(in_y);
        const float txf = floorf(in_x);
        s_ly[r] = in_y - tyf;
        s_lx[r] = in_x - txf;

        const int tyi = (int)tyf;
        const int txi = (int)txf;
        s_ty[r] = min(max(tyi,     0), H - 1);
        s_by[r] = min(max(tyi + 1, 0), H - 1);
        s_tx[r] = min(max(txi,     0), W - 1);
        s_bx[r] = min(max(txi + 1, 0), W - 1);
    }
    __syncthreads();

    // 64 float4 lanes cover C=256; 4 pool positions in flight per iteration
    const int c4 = (threadIdx.x & 63);           // float4 index within channel dim
    float* out_roi = out + (size_t)roi * (POOL * POOL * C_CH);

    #pragma unroll 4
    for (int p = (threadIdx.x >> 6); p < POOL * POOL; p += 4) {
        const int py = p / POOL;
        const int px = p - py * POOL;

        const int yT = s_ty[py], yB = s_by[py];
        const int xL = s_tx[px], xR = s_bx[px];
        const float ly = s_ly[py], lx = s_lx[px];

        const float4 tl = reinterpret_cast<const float4*>(
            fb + ((size_t)yT * W + xL) * C_CH)[c4];
        const float4 tr = reinterpret_cast<const float4*>(
            fb + ((size_t)yT * W + xR) * C_CH)[c4];
        const float4 bl = reinterpret_cast<const float4*>(
            fb + ((size_t)yB * W + xL) * C_CH)[c4];
        const float4 br = reinterpret_cast<const float4*>(
            fb + ((size_t)yB * W + xR) * C_CH)[c4];

        float4 o;
        {
            const float top = tl.x + (tr.x - tl.x) * lx;
            const float bot = bl.x + (br.x - bl.x) * lx;
            o.x = top + (bot - top) * ly;
        }
        {
            const float top = tl.y + (tr.y - tl.y) * lx;
            const float bot = bl.y + (br.y - bl.y) * lx;
            o.y = top + (bot - top) * ly;
        }
        {
            const float top = tl.z + (tr.z - tl.z) * lx;
            const float bot = bl.z + (br.z - bl.z) * lx;
            o.z = top + (bot - top) * ly;
        }
        {
            const float top = tl.w + (tr.w - tl.w) * lx;
            const float bot = bl.w + (br.w - bl.w) * lx;
            o.w = top + (bot - top) * ly;
        }

        reinterpret_cast<float4*>(out_roi + (size_t)p * C_CH)[c4] = o;
    }
}

extern "C" void kernel_launch(void* const* d_in, const int* in_sizes, int n_in,
                              void* d_out, int out_size)
{
    const float* f0    = (const float*)d_in[0];
    const float* f1    = (const float*)d_in[1];
    const float* f2    = (const float*)d_in[2];
    const float* f3    = (const float*)d_in[3];
    const float* props = (const float*)d_in[4];
    float* out = (float*)d_out;

    const int BN = in_sizes[4] / 4;                     // B*N rois
    const int B  = in_sizes[0] / (256 * 256 * 256);     // batch from feat0
    const int N  = (B > 0) ? (BN / B) : BN;

    roi_align_kernel<<<BN, 256>>>(f0, f1, f2, f3, props, out, N);
}

// round 4
// speedup vs baseline: 1.1491x; 1.1491x over previous
#include <cuda_runtime.h>
#include <cstddef>

// RoiAlign: 4-level FPN, B=2, N=1000, C=256, POOL=7
// out[B, N, 7, 7, C] float32
// Inputs: feat0 [2,256,256,256], feat1 [2,128,128,256],
//         feat2 [2,64,64,256],   feat3 [2,32,32,256],
//         proposals [2,1000,4]  (x1,y1,x2,y2 in [0,1])

#define POOL 7
#define C_CH 256
#define NPOS (POOL * POOL)   // 49

__global__ __launch_bounds__(256, 6)
void roi_align_kernel(const float* __restrict__ f0,
                      const float* __restrict__ f1,
                      const float* __restrict__ f2,
                      const float* __restrict__ f3,
                      const float* __restrict__ props,
                      float* __restrict__ out,
                      int N)
{
    const int roi = blockIdx.x;          // 0 .. B*N-1
    const int b   = roi / N;

    // box (uniform across block)
    const float4 box = reinterpret_cast<const float4*>(props)[roi];
    const float x1 = box.x, y1 = box.y, x2 = box.z, y2 = box.w;

    // ---- level selection (replicates reference fp32 math exactly) ----
    const float area  = (y2 - y1) * (x2 - x1);
    const float canon = 56.0f / 1024.0f + 1e-6f;
    const float lf = floorf(logf(sqrtf(area) / canon) / logf(2.0f));
    int lvl = 0;
    if (lf >= 3.0f)       lvl = 3;
    else if (lf >= 1.0f)  lvl = (int)lf;

    const int H = 256 >> lvl;
    const int W = 256 >> lvl;
    const float* f = (lvl == 0) ? f0 : (lvl == 1) ? f1 : (lvl == 2) ? f2 : f3;
    const char* fbb = (const char*)(f + (size_t)b * H * W * C_CH);

    // ---- per-position corner byte-offsets + weights, computed once ----
    __shared__ int4   s_off[NPOS];   // byte offsets of tl, tr, bl, br
    __shared__ float2 s_w[NPOS];     // (lx, ly)

    if (threadIdx.x < NPOS) {
        const int p  = threadIdx.x;
        const int py = p / POOL;
        const int px = p - py * POOL;

        const float Hf = (float)H - 1.0f;
        const float Wf = (float)W - 1.0f;

        const float in_y = y1 * Hf + (float)py * ((y2 - y1) * Hf / (float)(POOL - 1));
        const float in_x = x1 * Wf + (float)px * ((x2 - x1) * Wf / (float)(POOL - 1));

        const float tyf = floorf(in_y);
        const float txf = floorf(in_x);

        const int tyi = (int)tyf;
        const int txi = (int)txf;
        const int yT = min(max(tyi,     0), H - 1);
        const int yB = min(max(tyi + 1, 0), H - 1);
        const int xL = min(max(txi,     0), W - 1);
        const int xR = min(max(txi + 1, 0), W - 1);

        // row byte stride = W*C*4 = W*1024; pixel stride = 1024
        const int rT = yT * W;
        const int rB = yB * W;
        int4 o;
        o.x = (rT + xL) << 10;   // tl
        o.y = (rT + xR) << 10;   // tr
        o.z = (rB + xL) << 10;   // bl
        o.w = (rB + xR) << 10;   // br
        s_off[p] = o;
        s_w[p] = make_float2(in_x - txf, in_y - tyf);
    }
    __syncthreads();

    // 64 float4 lanes cover C=256; 4 pool positions in flight
    const int c16 = (threadIdx.x & 63) << 4;     // byte offset in channel dim
    const int pbase = threadIdx.x >> 6;          // 0..3
    char* out_roi = (char*)(out + (size_t)roi * (NPOS * C_CH)) + c16;

    #pragma unroll 2
    for (int p = pbase; p < NPOS; p += 4) {
        const int4   o = s_off[p];
        const float2 w = s_w[p];
        const float lx = w.x, ly = w.y;

        const float4 tl = *reinterpret_cast<const float4*>(fbb + o.x + c16);
        const float4 tr = *reinterpret_cast<const float4*>(fbb + o.y + c16);
        const float4 bl = *reinterpret_cast<const float4*>(fbb + o.z + c16);
        const float4 br = *reinterpret_cast<const float4*>(fbb + o.w + c16);

        float4 res;
        {
            const float top = tl.x + (tr.x - tl.x) * lx;
            const float bot = bl.x + (br.x - bl.x) * lx;
            res.x = top + (bot - top) * ly;
        }
        {
            const float top = tl.y + (tr.y - tl.y) * lx;
            const float bot = bl.y + (br.y - bl.y) * lx;
            res.y = top + (bot - top) * ly;
        }
        {
            const float top = tl.z + (tr.z - tl.z) * lx;
            const float bot = bl.z + (br.z - bl.z) * lx;
            res.z = top + (bot - top) * ly;
        }
        {
            const float top = tl.w + (tr.w - tl.w) * lx;
            const float bot = bl.w + (br.w - bl.w) * lx;
            res.w = top + (bot - top) * ly;
        }

        *reinterpret_cast<float4*>(out_roi + (p << 10)) = res;
    }
}

extern "C" void kernel_launch(void* const* d_in, const int* in_sizes, int n_in,
                              void* d_out, int out_size)
{
    const float* f0    = (const float*)d_in[0];
    const float* f1    = (const float*)d_in[1];
    const float* f2    = (const float*)d_in[2];
    const float* f3    = (const float*)d_in[3];
    const float* props = (const float*)d_in[4];
    float* out = (float*)d_out;

    const int BN = in_sizes[4] / 4;                     // B*N rois
    const int B  = in_sizes[0] / (256 * 256 * 256);     // batch from feat0
    const int N  = (B > 0) ? (BN / B) : BN;

    roi_align_kernel<<<BN, 256>>>(f0, f1, f2, f3, props, out, N);
}